// round 3
// baseline (speedup 1.0000x reference)
#include <cuda_runtime.h>
#include <math.h>

#define BATCH 8
#define LSEQ 4096
#define DM 512
#define UK 45
#define UQ 45
#define RTOT (BATCH*UK)
#define NSPLIT 8
#define PSCALE 0.044194173824159216f  // 1/sqrt(512)

__device__ float g_M[DM*DM];
__device__ float g_wkbq[DM];
__device__ float g_wvmean[DM];
__device__ float g_bvmean;
__device__ float g_G[RTOT*DM];
__device__ float g_c0[RTOT];
__device__ float g_meas[BATCH*LSEQ];
__device__ int   g_I[RTOT];
__device__ float g_H2[RTOT*DM];
__device__ float g_S[RTOT*LSEQ];
__device__ float g_AVp[NSPLIT*RTOT*DM];
__device__ float g_AV[RTOT*DM];
__device__ float g_s1[RTOT*DM];

__global__ void prep_kernel(const float* __restrict__ WV, const float* __restrict__ bV,
                            const float* __restrict__ WK, const float* __restrict__ bQ) {
    int i = threadIdx.x;  // 512
    if (blockIdx.x == 0) {
        float s = 0.f;
        const float* row = WV + i*DM;
        for (int j = 0; j < DM; j++) s += row[j];
        g_wvmean[i] = s * (1.0f/DM);
        __shared__ float red[512];
        red[i] = bV[i]; __syncthreads();
        for (int st = 256; st > 0; st >>= 1) { if (i < st) red[i] += red[i+st]; __syncthreads(); }
        if (i == 0) g_bvmean = red[0] * (1.0f/DM);
    } else {
        float s = 0.f;
        const float* row = WK + i*DM;
        for (int j = 0; j < DM; j++) s += row[j]*bQ[j];
        g_wkbq[i] = s;
    }
}

// C[m,n] = sum_k A[m,k] * (TRANSB ? B[n,k] : B[k,n]) (+bias[n]); N=K=512.
// GATHER: 0 none; 1 A row = (m/UK)*LSEQ + gidx[m]; 2 same with g_I.
template<int TRANSB, int GATHER, int BIAS>
__global__ void gemm512(const float* __restrict__ A, const float* __restrict__ Bm,
                        const float* __restrict__ bias, float* __restrict__ C,
                        int Mrows, const int* __restrict__ gidx) {
    const int BMt = 64, BNt = 64, BKt = 16;
    __shared__ float As[BKt][BMt+1];
    __shared__ float Bs[BKt][BNt+1];
    int tid = threadIdx.x;  // 256
    int tx = tid & 15, ty = tid >> 4;
    int n0 = blockIdx.x * BNt, m0 = blockIdx.y * BMt;
    float acc[4][4] = {};
    for (int k0 = 0; k0 < DM; k0 += BKt) {
        for (int i = tid; i < BMt*BKt; i += 256) {
            int m = i >> 4, kk = i & 15;
            int mm = m0 + m;
            float v = 0.f;
            if (mm < Mrows) {
                int arow;
                if (GATHER == 0)      arow = mm;
                else if (GATHER == 1) arow = (mm/UK)*LSEQ + gidx[mm];
                else                  arow = (mm/UK)*LSEQ + g_I[mm];
                v = A[arow*DM + k0 + kk];
            }
            As[kk][m] = v;
        }
        if (TRANSB) {
            for (int i = tid; i < BNt*BKt; i += 256) {
                int n = i >> 4, kk = i & 15;
                Bs[kk][n] = Bm[(n0+n)*DM + k0 + kk];
            }
        } else {
            for (int i = tid; i < BKt*BNt; i += 256) {
                int kk = i >> 6, n = i & 63;
                Bs[kk][n] = Bm[(k0+kk)*DM + n0 + n];
            }
        }
        __syncthreads();
        #pragma unroll
        for (int kk = 0; kk < BKt; kk++) {
            float a[4], b[4];
            #pragma unroll
            for (int i = 0; i < 4; i++) a[i] = As[kk][ty + 16*i];
            #pragma unroll
            for (int j = 0; j < 4; j++) b[j] = Bs[kk][tx + 16*j];
            #pragma unroll
            for (int i = 0; i < 4; i++)
                #pragma unroll
                for (int j = 0; j < 4; j++) acc[i][j] += a[i]*b[j];
        }
        __syncthreads();
    }
    #pragma unroll
    for (int i = 0; i < 4; i++) {
        int mm = m0 + ty + 16*i;
        if (mm >= Mrows) continue;
        #pragma unroll
        for (int j = 0; j < 4; j++) {
            float v = acc[i][j];
            if (BIAS) v += bias[n0 + tx + 16*j];
            C[mm*DM + n0 + tx + 16*j] = v;
        }
    }
}

__global__ void c0_kernel(const float* __restrict__ K, const int* __restrict__ kidx) {
    int r = blockIdx.x;  // RTOT
    int b = r / UK;
    const float* krow = K + ((long)b*LSEQ + kidx[r])*DM;
    float s = 0.f;
    for (int j = threadIdx.x; j < DM; j += 128) s += krow[j]*g_wkbq[j];
    __shared__ float red[128];
    red[threadIdx.x] = s; __syncthreads();
    for (int st = 64; st > 0; st >>= 1) {
        if (threadIdx.x < st) red[threadIdx.x] += red[threadIdx.x+st];
        __syncthreads();
    }
    if (threadIdx.x == 0) g_c0[r] = red[0];
}

// Z[l,u] = X[b,l,:].Y[u,:], 46 virtual rows.
// MODE 0: Y=G rows (u<45) else 0; epilogue meas = max(z+c0) - mean(z+c0).
// MODE 1: Y=H2 rows (u<45) else wkbq; writes S[u][l] = (z_u + z_45)*PSCALE.
template<int MODE>
__global__ void tall46(const float* __restrict__ X) {
    const int BM = 128, BK = 32, NU = 46;
    __shared__ float Xs[BK][BM+1];
    __shared__ float Ys[NU][BK];
    __shared__ float c0s[UK];
    int b  = blockIdx.y;
    int l0 = blockIdx.x * BM;
    int tid = threadIdx.x;  // 128
    if (MODE == 0 && tid < UK) c0s[tid] = g_c0[b*UK + tid];
    float acc[NU];
    #pragma unroll
    for (int u = 0; u < NU; u++) acc[u] = 0.f;
    const float* Xb = X + ((long)b*LSEQ + l0)*DM;
    for (int k0 = 0; k0 < DM; k0 += BK) {
        for (int i = tid; i < BM*BK; i += 128) {
            int kk = i & 31, r = i >> 5;
            Xs[kk][r] = Xb[r*DM + k0 + kk];
        }
        for (int i = tid; i < NU*(BK/4); i += 128) {
            int u = i >> 3, c4 = i & 7;
            float4 v;
            if (MODE == 0) {
                if (u < UK) v = *reinterpret_cast<const float4*>(&g_G[(b*UK+u)*DM + k0 + c4*4]);
                else        v = make_float4(0.f,0.f,0.f,0.f);
            } else {
                if (u < UK) v = *reinterpret_cast<const float4*>(&g_H2[(b*UK+u)*DM + k0 + c4*4]);
                else        v = *reinterpret_cast<const float4*>(&g_wkbq[k0 + c4*4]);
            }
            *reinterpret_cast<float4*>(&Ys[u][c4*4]) = v;
        }
        __syncthreads();
        #pragma unroll
        for (int c4 = 0; c4 < BK/4; c4++) {
            float x0 = Xs[c4*4+0][tid];
            float x1 = Xs[c4*4+1][tid];
            float x2 = Xs[c4*4+2][tid];
            float x3 = Xs[c4*4+3][tid];
            #pragma unroll
            for (int u = 0; u < NU; u++) {
                float4 y = *reinterpret_cast<const float4*>(&Ys[u][c4*4]);
                acc[u] += x0*y.x; acc[u] += x1*y.y;
                acc[u] += x2*y.z; acc[u] += x3*y.w;
            }
        }
        __syncthreads();
    }
    int l = l0 + tid;
    if (MODE == 0) {
        float m = -INFINITY, s = 0.f;
        #pragma unroll
        for (int u = 0; u < UK; u++) {
            float v = acc[u] + c0s[u];
            m = fmaxf(m, v); s += v;
        }
        g_meas[b*LSEQ + l] = m - s*(1.0f/UK);
    } else {
        float ck = acc[UK];
        #pragma unroll
        for (int u = 0; u < UQ; u++)
            g_S[((long)b*UQ + u)*LSEQ + l] = (acc[u] + ck) * PSCALE;
    }
}

__global__ void topk_kernel() {
    __shared__ float vals[LSEQ];
    __shared__ float wvs[32];
    __shared__ int   wis[32];
    int b = blockIdx.x, tid = threadIdx.x;  // 1024
    int lane = tid & 31, w = tid >> 5;
    for (int i = tid; i < LSEQ; i += 1024) vals[i] = g_meas[b*LSEQ + i];
    __syncthreads();
    for (int it = 0; it < UQ; it++) {
        float bv = -INFINITY; int bi = 0x7fffffff;
        for (int i = tid; i < LSEQ; i += 1024) {
            float v = vals[i];
            if (v > bv) { bv = v; bi = i; }
        }
        #pragma unroll
        for (int off = 16; off > 0; off >>= 1) {
            float ov = __shfl_xor_sync(~0u, bv, off);
            int   oi = __shfl_xor_sync(~0u, bi, off);
            if (ov > bv || (ov == bv && oi < bi)) { bv = ov; bi = oi; }
        }
        if (lane == 0) { wvs[w] = bv; wis[w] = bi; }
        __syncthreads();
        if (w == 0) {
            bv = wvs[lane]; bi = wis[lane];
            #pragma unroll
            for (int off = 16; off > 0; off >>= 1) {
                float ov = __shfl_xor_sync(~0u, bv, off);
                int   oi = __shfl_xor_sync(~0u, bi, off);
                if (ov > bv || (ov == bv && oi < bi)) { bv = ov; bi = oi; }
            }
            if (lane == 0) { g_I[b*UQ + it] = bi; vals[bi] = -INFINITY; }
        }
        __syncthreads();
    }
}

__global__ void softmax_kernel() {
    int p = blockIdx.x;
    float* row = g_S + (long)p*LSEQ;
    __shared__ float red[256];
    int tid = threadIdx.x;
    float m = -INFINITY;
    for (int i = tid; i < LSEQ; i += 256) m = fmaxf(m, row[i]);
    red[tid] = m; __syncthreads();
    for (int st = 128; st > 0; st >>= 1) { if (tid < st) red[tid] = fmaxf(red[tid], red[tid+st]); __syncthreads(); }
    m = red[0]; __syncthreads();
    float s = 0.f;
    for (int i = tid; i < LSEQ; i += 256) s += expf(row[i] - m);
    red[tid] = s; __syncthreads();
    for (int st = 128; st > 0; st >>= 1) { if (tid < st) red[tid] += red[tid+st]; __syncthreads(); }
    float inv = 1.0f / red[0];
    for (int i = tid; i < LSEQ; i += 256) row[i] = expf(row[i] - m) * inv;
}

__global__ void av_kernel(const float* __restrict__ V) {
    const int BMp = 48, BNt = 128, BKt = 16;
    __shared__ float As[BMp][BKt+1];
    __shared__ float Bs[BKt][BNt+4];
    int b  = blockIdx.z, kc = blockIdx.y;
    int n0 = blockIdx.x * BNt;
    int tid = threadIdx.x;  // 256
    int tx = tid & 15, ty = tid >> 4;
    float acc[3][8] = {};
    for (int kb = 0; kb < LSEQ/NSPLIT; kb += BKt) {
        int kg = kc*(LSEQ/NSPLIT) + kb;
        for (int i = tid; i < BMp*BKt; i += 256) {
            int u = i >> 4, kk = i & 15;
            As[u][kk] = (u < UQ) ? g_S[((long)b*UQ+u)*LSEQ + kg + kk] : 0.f;
        }
        for (int i = tid; i < BKt*BNt; i += 256) {
            int kk = i >> 7, n = i & 127;
            Bs[kk][n] = V[((long)b*LSEQ + kg + kk)*DM + n0 + n];
        }
        __syncthreads();
        #pragma unroll
        for (int kk = 0; kk < BKt; kk++) {
            float a[3], bb[8];
            #pragma unroll
            for (int i = 0; i < 3; i++) a[i] = As[ty + 16*i][kk];
            #pragma unroll
            for (int j = 0; j < 8; j++) bb[j] = Bs[kk][tx + 16*j];
            #pragma unroll
            for (int i = 0; i < 3; i++)
                #pragma unroll
                for (int j = 0; j < 8; j++) acc[i][j] += a[i]*bb[j];
        }
        __syncthreads();
    }
    #pragma unroll
    for (int i = 0; i < 3; i++) {
        int u = ty + 16*i;
        if (u >= UQ) continue;
        int r = b*UQ + u;
        #pragma unroll
        for (int j = 0; j < 8; j++)
            g_AVp[((long)kc*RTOT + r)*DM + n0 + tx + 16*j] = acc[i][j];
    }
}

__global__ void avreduce_kernel() {
    int idx = blockIdx.x*256 + threadIdx.x;
    if (idx >= RTOT*DM) return;
    float s = 0.f;
    #pragma unroll
    for (int kc = 0; kc < NSPLIT; kc++) s += g_AVp[kc*RTOT*DM + idx];
    g_AV[idx] = s;
}

__global__ void base_kernel(const float* __restrict__ V, float* __restrict__ out) {
    int w = threadIdx.x >> 5, lane = threadIdx.x & 31;
    long row = (long)blockIdx.x*8 + w;
    const float4* v4 = reinterpret_cast<const float4*>(V + row*DM);
    const float4* w4 = reinterpret_cast<const float4*>(g_wvmean);
    float s = 0.f;
    #pragma unroll
    for (int i = 0; i < 4; i++) {
        float4 a = v4[lane + 32*i];
        float4 c = w4[lane + 32*i];
        s += a.x*c.x + a.y*c.y + a.z*c.z + a.w*c.w;
    }
    #pragma unroll
    for (int off = 16; off > 0; off >>= 1) s += __shfl_xor_sync(0xffffffffu, s, off);
    float r = s + g_bvmean;
    float4 o = make_float4(r, r, r, r);
    float4* o4 = reinterpret_cast<float4*>(out + row*DM);
    #pragma unroll
    for (int i = 0; i < 4; i++) o4[lane + 32*i] = o;
}

__global__ void scatter_kernel(float* __restrict__ out) {
    int r = blockIdx.x;  // RTOT
    int b = r / UQ;
    long row = (long)b*LSEQ + g_I[r];
    const float4* s4 = reinterpret_cast<const float4*>(g_s1 + (long)r*DM);
    float4* o4 = reinterpret_cast<float4*>(out + row*DM);
    o4[threadIdx.x] = s4[threadIdx.x];  // 128 x float4
}

extern "C" void kernel_launch(void* const* d_in, const int* in_sizes, int n_in,
                              void* d_out, int out_size) {
    (void)in_sizes; (void)n_in; (void)out_size;
    const float* Q  = (const float*)d_in[0];
    const float* K  = (const float*)d_in[1];
    const float* V  = (const float*)d_in[2];
    const float* WQ = (const float*)d_in[3];
    const float* bQ = (const float*)d_in[4];
    const float* WK = (const float*)d_in[5];
    const float* WV = (const float*)d_in[7];
    const float* bV = (const float*)d_in[8];
    const int* kidx = (const int*)d_in[9];
    float* out = (float*)d_out;

    float *pM, *pG, *pH2, *pAV, *ps1;
    cudaGetSymbolAddress((void**)&pM,  g_M);
    cudaGetSymbolAddress((void**)&pG,  g_G);
    cudaGetSymbolAddress((void**)&pH2, g_H2);
    cudaGetSymbolAddress((void**)&pAV, g_AV);
    cudaGetSymbolAddress((void**)&ps1, g_s1);

    prep_kernel<<<2, 512>>>(WV, bV, WK, bQ);
    gemm512<1,0,0><<<dim3(8,8), 256>>>(WQ, WK, nullptr, pM, 512, nullptr);   // M = WQ WK^T
    gemm512<1,1,0><<<dim3(8,6), 256>>>(K, pM, nullptr, pG, RTOT, kidx);      // G = K[idx] M^T
    c0_kernel<<<RTOT, 128>>>(K, kidx);
    tall46<0><<<dim3(LSEQ/128, BATCH), 128>>>(Q);                            // meas
    topk_kernel<<<BATCH, 1024>>>();
    gemm512<0,2,0><<<dim3(8,6), 256>>>(Q, pM, nullptr, pH2, RTOT, nullptr);  // H2 = Q[I] M
    tall46<1><<<dim3(LSEQ/128, BATCH), 128>>>(K);                            // logits
    softmax_kernel<<<RTOT, 256>>>();
    av_kernel<<<dim3(4, NSPLIT, BATCH), 256>>>(V);
    avreduce_kernel<<<(RTOT*DM + 255)/256, 256>>>();
    gemm512<0,0,1><<<dim3(8,6), 256>>>(pAV, WV, bV, ps1, RTOT, nullptr);     // s1 = AV WV + bV
    base_kernel<<<BATCH*LSEQ/8, 256>>>(V, out);
    scatter_kernel<<<RTOT, 128>>>(out);
}

// round 5
// speedup vs baseline: 2.3216x; 2.3216x over previous
#include <cuda_runtime.h>
#include <stdint.h>
#include <math.h>

#define BATCH 8
#define LSEQ 4096
#define DM 512
#define UK 45
#define UQ 45
#define RTOT (BATCH*UK)
#define NSPLIT 8
#define PSCALE 0.044194173824159216f  // 1/sqrt(512)

__device__ float g_M[DM*DM];
__device__ float g_wkbq[DM];
__device__ float g_wvmean[DM];
__device__ float g_bvmean;
__device__ float g_G[RTOT*DM];
__device__ float g_c0[RTOT];
__device__ float g_meas[BATCH*LSEQ];
__device__ int   g_I[RTOT];
__device__ float g_H2[RTOT*DM];
__device__ float g_S[RTOT*LSEQ];
__device__ float g_AVp[NSPLIT*RTOT*DM];
__device__ float g_AV[RTOT*DM];

__device__ __forceinline__ unsigned sptr(const void* p) {
    return (unsigned)__cvta_generic_to_shared(p);
}
__device__ __forceinline__ void cpa16(unsigned s, const void* g) {
    asm volatile("cp.async.cg.shared.global [%0], [%1], 16;" :: "r"(s), "l"(g));
}
__device__ __forceinline__ void cpa_commit() {
    asm volatile("cp.async.commit_group;" ::: "memory");
}
__device__ __forceinline__ void cpa_wait1() {
    asm volatile("cp.async.wait_group 1;" ::: "memory");
}
__device__ __forceinline__ void cpa_wait0() {
    asm volatile("cp.async.wait_group 0;" ::: "memory");
}

// ---------------- prep: wvmean (blocks 0-31), wkbq (32-63), bvmean (64) ----------------
__global__ void prep_kernel(const float* __restrict__ WV, const float* __restrict__ bV,
                            const float* __restrict__ WK, const float* __restrict__ bQ) {
    int bid = blockIdx.x, tid = threadIdx.x;  // 512 thr
    int w = tid >> 5, lane = tid & 31;
    if (bid < 32) {
        int row = bid*16 + w;
        float s = 0.f;
        #pragma unroll
        for (int j = 0; j < 16; j++) s += WV[row*DM + lane + 32*j];
        #pragma unroll
        for (int o = 16; o > 0; o >>= 1) s += __shfl_xor_sync(~0u, s, o);
        if (lane == 0) g_wvmean[row] = s * (1.0f/DM);
    } else if (bid < 64) {
        int row = (bid-32)*16 + w;
        float s = 0.f;
        #pragma unroll
        for (int j = 0; j < 16; j++) {
            int c = lane + 32*j;
            s += WK[row*DM + c] * bQ[c];
        }
        #pragma unroll
        for (int o = 16; o > 0; o >>= 1) s += __shfl_xor_sync(~0u, s, o);
        if (lane == 0) g_wkbq[row] = s;
    } else {
        __shared__ float red[512];
        red[tid] = bV[tid]; __syncthreads();
        for (int st = 256; st > 0; st >>= 1) { if (tid < st) red[tid] += red[tid+st]; __syncthreads(); }
        if (tid == 0) g_bvmean = red[0] * (1.0f/DM);
    }
}

// ---------------- gemm512: C = A * (B or B^T) (+bias); N=K=512, double-buffered ----------------
// GATHER: 0 none; 1 arow=(m/UK)*LSEQ+gidx[m]; 2 same w/ g_I. SCATTER: write to out row b*LSEQ+g_I[m].
template<int TRANSB, int GATHER, int BIAS, int SCATTER>
__global__ void gemm512(const float* __restrict__ A, const float* __restrict__ Bm,
                        const float* __restrict__ bias, float* __restrict__ C,
                        int Mrows, const int* __restrict__ gidx) {
    const int BK = 32;
    __shared__ float As[2][64][36];
    __shared__ float BsT[TRANSB ? 2 : 1][TRANSB ? 64 : 1][TRANSB ? 36 : 1];
    __shared__ float BsN[TRANSB ? 1 : 2][TRANSB ? 1 : 32][TRANSB ? 1 : 68];
    int tid = threadIdx.x;  // 256
    int tx = tid & 15, ty = tid >> 4;
    int n0 = blockIdx.x * 64, m0 = blockIdx.y * 64;
    float acc[4][4] = {};

    auto load_tile = [&](int t, int buf) {
        int k0 = t * BK;
        #pragma unroll
        for (int j = 0; j < 2; j++) {
            int c = tid + 256*j;           // 512 chunks: 64 rows x 8 quads
            int r = c >> 3, q = c & 7;
            int mm = m0 + r;
            if (mm < Mrows) {
                int arow;
                if (GATHER == 0)      arow = mm;
                else if (GATHER == 1) arow = (mm/UK)*LSEQ + gidx[mm];
                else                  arow = (mm/UK)*LSEQ + g_I[mm];
                cpa16(sptr(&As[buf][r][q*4]), A + (long)arow*DM + k0 + q*4);
            } else {
                *(float4*)&As[buf][r][q*4] = make_float4(0.f,0.f,0.f,0.f);
            }
        }
        if (TRANSB) {
            #pragma unroll
            for (int j = 0; j < 2; j++) {
                int c = tid + 256*j;
                int r = c >> 3, q = c & 7;
                cpa16(sptr(&BsT[buf][r][q*4]), Bm + (long)(n0+r)*DM + k0 + q*4);
            }
        } else {
            #pragma unroll
            for (int j = 0; j < 2; j++) {
                int c = tid + 256*j;       // 512 chunks: 32 k x 16 quads
                int kk = c >> 4, q = c & 15;
                cpa16(sptr(&BsN[buf][kk][q*4]), Bm + (long)(k0+kk)*DM + n0 + q*4);
            }
        }
        cpa_commit();
    };

    load_tile(0, 0);
    const int NT = DM / BK;
    for (int t = 0; t < NT; t++) {
        int buf = t & 1;
        if (t+1 < NT) { load_tile(t+1, buf^1); cpa_wait1(); } else cpa_wait0();
        __syncthreads();
        #pragma unroll
        for (int kk = 0; kk < BK; kk++) {
            float a[4], b[4];
            #pragma unroll
            for (int i = 0; i < 4; i++) a[i] = As[buf][ty + 16*i][kk];
            #pragma unroll
            for (int j = 0; j < 4; j++) b[j] = TRANSB ? BsT[buf][tx + 16*j][kk]
                                                      : BsN[buf][kk][tx + 16*j];
            #pragma unroll
            for (int i = 0; i < 4; i++)
                #pragma unroll
                for (int j = 0; j < 4; j++) acc[i][j] = fmaf(a[i], b[j], acc[i][j]);
        }
        __syncthreads();
    }
    #pragma unroll
    for (int i = 0; i < 4; i++) {
        int mm = m0 + ty + 16*i;
        if (mm >= Mrows) continue;
        long orow = SCATTER ? ((long)(mm/UK)*LSEQ + g_I[mm]) : mm;
        #pragma unroll
        for (int j = 0; j < 4; j++) {
            float v = acc[i][j];
            if (BIAS) v += bias[n0 + tx + 16*j];
            C[orow*DM + n0 + tx + 16*j] = v;
        }
    }
}

// ---------------- c0[r] = kbar_r . wkbq ----------------
__global__ void c0_kernel(const float* __restrict__ K, const int* __restrict__ kidx) {
    int r = blockIdx.x;
    int b = r / UK;
    const float* krow = K + ((long)b*LSEQ + kidx[r])*DM;
    int lane = threadIdx.x & 31, w = threadIdx.x >> 5;  // 128 thr
    float s = 0.f;
    #pragma unroll
    for (int j = 0; j < 4; j++) {
        int c = w*128 + lane + 32*j;
        s += krow[c]*g_wkbq[c];
    }
    #pragma unroll
    for (int o = 16; o > 0; o >>= 1) s += __shfl_xor_sync(~0u, s, o);
    __shared__ float red[4];
    if (lane == 0) red[w] = s;
    __syncthreads();
    if (threadIdx.x == 0) g_c0[r] = red[0]+red[1]+red[2]+red[3];
}

// ---------------- tall46: Z[l,u]=X[b,l,:].Y[u,:] (46 virtual rows), double-buffered ----------------
// MODE0: Y=G, row45=0; epilogue meas = max(z+c0)-mean(z+c0).
// MODE1: Y=H2, row45=wkbq; writes S[u][l]=(z_u+z_45)*PSCALE.
template<int MODE>
__global__ void tall46(const float* __restrict__ X) {
    const int BM = 128, BK = 16, NU = 46;
    __shared__ float Xs[2][BM][20];
    __shared__ float Ys[2][NU][BK];
    __shared__ float c0s[UK];
    int b = blockIdx.y, l0 = blockIdx.x * BM, tid = threadIdx.x;  // 128
    if (MODE == 0 && tid < UK) c0s[tid] = g_c0[b*UK + tid];
    float acc[NU];
    #pragma unroll
    for (int u = 0; u < NU; u++) acc[u] = 0.f;
    const float* Xb = X + ((long)b*LSEQ + l0)*DM;

    auto load_tile = [&](int t, int buf) {
        int k0 = t * BK;
        #pragma unroll
        for (int j = 0; j < 4; j++) {
            int c = tid + 128*j;           // 512 chunks: 128 rows x 4 quads
            int r = c >> 2, q = c & 3;
            cpa16(sptr(&Xs[buf][r][q*4]), Xb + (long)r*DM + k0 + q*4);
        }
        #pragma unroll
        for (int j = 0; j < 2; j++) {
            int c = tid + 128*j;           // 184 chunks: 46 rows x 4 quads
            if (c < NU*4) {
                int u = c >> 2, q = c & 3;
                if (u < UK) {
                    const float* src = (MODE == 0) ? &g_G[(long)(b*UK+u)*DM + k0 + q*4]
                                                   : &g_H2[(long)(b*UK+u)*DM + k0 + q*4];
                    cpa16(sptr(&Ys[buf][u][q*4]), src);
                } else {
                    if (MODE == 0) *(float4*)&Ys[buf][u][q*4] = make_float4(0.f,0.f,0.f,0.f);
                    else cpa16(sptr(&Ys[buf][u][q*4]), &g_wkbq[k0 + q*4]);
                }
            }
        }
        cpa_commit();
    };

    load_tile(0, 0);
    const int NT = DM / BK;
    for (int t = 0; t < NT; t++) {
        int buf = t & 1;
        if (t+1 < NT) { load_tile(t+1, buf^1); cpa_wait1(); } else cpa_wait0();
        __syncthreads();
        #pragma unroll
        for (int c4 = 0; c4 < BK/4; c4++) {
            float4 x = *(const float4*)&Xs[buf][tid][c4*4];
            #pragma unroll
            for (int u = 0; u < NU; u++) {
                float4 y = *(const float4*)&Ys[buf][u][c4*4];
                acc[u] = fmaf(x.x, y.x, acc[u]);
                acc[u] = fmaf(x.y, y.y, acc[u]);
                acc[u] = fmaf(x.z, y.z, acc[u]);
                acc[u] = fmaf(x.w, y.w, acc[u]);
            }
        }
        __syncthreads();
    }
    int l = l0 + tid;
    if (MODE == 0) {
        float m = -INFINITY, s = 0.f;
        #pragma unroll
        for (int u = 0; u < UK; u++) {
            float v = acc[u] + c0s[u];
            m = fmaxf(m, v); s += v;
        }
        g_meas[b*LSEQ + l] = m - s*(1.0f/UK);
    } else {
        float ck = acc[UK];
        #pragma unroll
        for (int u = 0; u < UQ; u++)
            g_S[((long)b*UQ + u)*LSEQ + l] = (acc[u] + ck) * PSCALE;
    }
}

// ---------------- exact top-45 via 3-level radix select (set semantics; ties -> lowest idx) ----------------
__global__ void topk_kernel() {
    __shared__ unsigned um[LSEQ];
    __shared__ int hist[2048];
    __shared__ int eqbuf[256];
    __shared__ int s_rem, s_ngt, s_cntgt, s_cnteq;
    __shared__ unsigned s_prefmask, s_prefval;
    int b = blockIdx.x, tid = threadIdx.x;  // 512
    for (int i = tid; i < LSEQ; i += 512) {
        unsigned u = __float_as_uint(g_meas[b*LSEQ + i]);
        um[i] = (u & 0x80000000u) ? ~u : (u | 0x80000000u);
    }
    if (tid == 0) { s_rem = UQ; s_ngt = 0; s_prefmask = 0u; s_prefval = 0u; s_cntgt = 0; s_cnteq = 0; }
    __syncthreads();

    const int shifts[3] = {21, 10, 0};
    const unsigned bmask[3] = {0x7FFu, 0x7FFu, 0x3FFu};
    const int nbins[3] = {2048, 2048, 1024};
    for (int lev = 0; lev < 3; lev++) {
        for (int i = tid; i < nbins[lev]; i += 512) hist[i] = 0;
        __syncthreads();
        unsigned pm = s_prefmask, pv = s_prefval;
        for (int i = tid; i < LSEQ; i += 512) {
            unsigned k = um[i];
            if ((k & pm) == pv)
                atomicAdd(&hist[(k >> shifts[lev]) & bmask[lev]], 1);
        }
        __syncthreads();
        if (tid == 0) {
            int rem = s_rem, cum = 0, bsel = 0;
            for (int bin = nbins[lev]-1; bin >= 0; bin--) {
                cum += hist[bin];
                if (cum >= rem) { bsel = bin; break; }
            }
            s_ngt += cum - hist[bsel];
            s_rem = rem - (cum - hist[bsel]);
            s_prefmask |= bmask[lev] << shifts[lev];
            s_prefval  |= ((unsigned)bsel) << shifts[lev];
        }
        __syncthreads();
    }
    unsigned T = s_prefval;
    int n_gt = s_ngt;
    int need_eq = UQ - n_gt;
    for (int i = tid; i < LSEQ; i += 512) {
        unsigned k = um[i];
        if (k > T) {
            int p = atomicAdd(&s_cntgt, 1);
            g_I[b*UQ + p] = i;
        } else if (k == T) {
            int p = atomicAdd(&s_cnteq, 1);
            if (p < 256) eqbuf[p] = i;
        }
    }
    __syncthreads();
    if (tid == 0) {
        int ne = s_cnteq; if (ne > 256) ne = 256;
        for (int j = 0; j < need_eq; j++) {
            int bi = 0x7fffffff, bp = -1;
            for (int q = 0; q < ne; q++)
                if (eqbuf[q] < bi) { bi = eqbuf[q]; bp = q; }
            eqbuf[bp] = 0x7fffffff;
            g_I[b*UQ + n_gt + j] = bi;
        }
    }
}

// ---------------- softmax over L, register-resident ----------------
__global__ void softmax_kernel() {
    float* row = g_S + (long)blockIdx.x*LSEQ;
    int tid = threadIdx.x;  // 256
    int lane = tid & 31, w = tid >> 5;
    __shared__ float red[8];
    float v[16];
    #pragma unroll
    for (int i = 0; i < 16; i++) v[i] = row[tid + 256*i];
    float m = -INFINITY;
    #pragma unroll
    for (int i = 0; i < 16; i++) m = fmaxf(m, v[i]);
    #pragma unroll
    for (int o = 16; o > 0; o >>= 1) m = fmaxf(m, __shfl_xor_sync(~0u, m, o));
    if (lane == 0) red[w] = m;
    __syncthreads();
    m = red[0];
    #pragma unroll
    for (int i = 1; i < 8; i++) m = fmaxf(m, red[i]);
    float e[16], s = 0.f;
    #pragma unroll
    for (int i = 0; i < 16; i++) { e[i] = expf(v[i] - m); s += e[i]; }
    #pragma unroll
    for (int o = 16; o > 0; o >>= 1) s += __shfl_xor_sync(~0u, s, o);
    __syncthreads();
    if (lane == 0) red[w] = s;
    __syncthreads();
    s = 0.f;
    #pragma unroll
    for (int i = 0; i < 8; i++) s += red[i];
    float inv = 1.0f / s;
    #pragma unroll
    for (int i = 0; i < 16; i++) row[tid + 256*i] = e[i] * inv;
}

// ---------------- attn @ V, K-split partials, double-buffered ----------------
__global__ void av_kernel(const float* __restrict__ V) {
    const int BKt = 32;
    __shared__ float As[2][48][36];
    __shared__ float Bs[2][32][132];
    int b = blockIdx.z, kc = blockIdx.y;
    int n0 = blockIdx.x * 128;
    int tid = threadIdx.x;  // 256
    int tx = tid & 15, ty = tid >> 4;
    float acc[3][8] = {};
    int kbase = kc * (LSEQ/NSPLIT);

    auto load_tile = [&](int t, int buf) {
        int kg = kbase + t*BKt;
        #pragma unroll
        for (int j = 0; j < 2; j++) {
            int c = tid + 256*j;            // 384 chunks: 48 rows x 8 quads
            if (c < 384) {
                int u = c >> 3, q = c & 7;
                if (u < UQ) cpa16(sptr(&As[buf][u][q*4]), &g_S[((long)b*UQ+u)*LSEQ + kg + q*4]);
                else        *(float4*)&As[buf][u][q*4] = make_float4(0.f,0.f,0.f,0.f);
            }
        }
        #pragma unroll
        for (int j = 0; j < 4; j++) {
            int c = tid + 256*j;            // 1024 chunks: 32 k x 32 quads
            int kk = c >> 5, q = c & 31;
            cpa16(sptr(&Bs[buf][kk][q*4]), V + ((long)b*LSEQ + kg + kk)*DM + n0 + q*4);
        }
        cpa_commit();
    };

    load_tile(0, 0);
    const int NT = (LSEQ/NSPLIT)/BKt;  // 16
    for (int t = 0; t < NT; t++) {
        int buf = t & 1;
        if (t+1 < NT) { load_tile(t+1, buf^1); cpa_wait1(); } else cpa_wait0();
        __syncthreads();
        #pragma unroll
        for (int kk = 0; kk < BKt; kk++) {
            float a[3], bb[8];
            #pragma unroll
            for (int i = 0; i < 3; i++) a[i] = As[buf][ty + 16*i][kk];
            #pragma unroll
            for (int j = 0; j < 8; j++) bb[j] = Bs[buf][kk][tx + 16*j];
            #pragma unroll
            for (int i = 0; i < 3; i++)
                #pragma unroll
                for (int j = 0; j < 8; j++) acc[i][j] = fmaf(a[i], bb[j], acc[i][j]);
        }
        __syncthreads();
    }
    #pragma unroll
    for (int i = 0; i < 3; i++) {
        int u = ty + 16*i;
        if (u >= UQ) continue;
        int r = b*UQ + u;
        #pragma unroll
        for (int j = 0; j < 8; j++)
            g_AVp[((long)kc*RTOT + r)*DM + n0 + tx + 16*j] = acc[i][j];
    }
}

__global__ void avreduce_kernel() {
    int idx = blockIdx.x*256 + threadIdx.x;
    if (idx >= RTOT*DM) return;
    float s = 0.f;
    #pragma unroll
    for (int kc = 0; kc < NSPLIT; kc++) s += g_AVp[(long)kc*RTOT*DM + idx];
    g_AV[idx] = s;
}

// ---------------- base rows: out[b,l,:] = V[b,l].wvmean + bvmean ----------------
__global__ void base_kernel(const float* __restrict__ V, float* __restrict__ out) {
    int w = threadIdx.x >> 5, lane = threadIdx.x & 31;
    long row = (long)blockIdx.x*8 + w;
    const float4* v4 = reinterpret_cast<const float4*>(V + row*DM);
    const float4* w4 = reinterpret_cast<const float4*>(g_wvmean);
    float s = 0.f;
    #pragma unroll
    for (int i = 0; i < 4; i++) {
        float4 a = v4[lane + 32*i];
        float4 c = w4[lane + 32*i];
        s += a.x*c.x + a.y*c.y + a.z*c.z + a.w*c.w;
    }
    #pragma unroll
    for (int o = 16; o > 0; o >>= 1) s += __shfl_xor_sync(~0u, s, o);
    float r = s + g_bvmean;
    float4 ov = make_float4(r, r, r, r);
    float4* o4 = reinterpret_cast<float4*>(out + row*DM);
    #pragma unroll
    for (int i = 0; i < 4; i++) o4[lane + 32*i] = ov;
}

extern "C" void kernel_launch(void* const* d_in, const int* in_sizes, int n_in,
                              void* d_out, int out_size) {
    (void)in_sizes; (void)n_in; (void)out_size;
    const float* Q  = (const float*)d_in[0];
    const float* K  = (const float*)d_in[1];
    const float* V  = (const float*)d_in[2];
    const float* WQ = (const float*)d_in[3];
    const float* bQ = (const float*)d_in[4];
    const float* WK = (const float*)d_in[5];
    const float* WV = (const float*)d_in[7];
    const float* bV = (const float*)d_in[8];
    const int* kidx = (const int*)d_in[9];
    float* out = (float*)d_out;

    float *pM, *pG, *pH2, *pAV;
    cudaGetSymbolAddress((void**)&pM,  g_M);
    cudaGetSymbolAddress((void**)&pG,  g_G);
    cudaGetSymbolAddress((void**)&pH2, g_H2);
    cudaGetSymbolAddress((void**)&pAV, g_AV);

    prep_kernel<<<65, 512>>>(WV, bV, WK, bQ);
    gemm512<1,0,0,0><<<dim3(8,8), 256>>>(WQ, WK, nullptr, pM, 512, nullptr);   // M = WQ WK^T
    gemm512<1,1,0,0><<<dim3(8,6), 256>>>(K, pM, nullptr, pG, RTOT, kidx);      // G = K[idx] M^T
    c0_kernel<<<RTOT, 128>>>(K, kidx);
    tall46<0><<<dim3(LSEQ/128, BATCH), 128>>>(Q);                              // meas
    topk_kernel<<<BATCH, 512>>>();
    gemm512<0,2,0,0><<<dim3(8,6), 256>>>(Q, pM, nullptr, pH2, RTOT, nullptr);  // H2 = Q[I] M
    tall46<1><<<dim3(LSEQ/128, BATCH), 128>>>(K);                              // logits
    softmax_kernel<<<RTOT, 256>>>();
    av_kernel<<<dim3(4, NSPLIT, BATCH), 256>>>(V);
    avreduce_kernel<<<(RTOT*DM + 255)/256, 256>>>();
    base_kernel<<<BATCH*LSEQ/8, 256>>>(V, out);
    gemm512<0,0,1,1><<<dim3(8,6), 256>>>(pAV, WV, bV, out, RTOT, nullptr);     // s1 -> scattered out
}

// round 6
// speedup vs baseline: 2.4835x; 1.0697x over previous
#include <cuda_runtime.h>
#include <stdint.h>
#include <math.h>

#define BATCH 8
#define LSEQ 4096
#define DM 512
#define UK 45
#define UQ 45
#define RTOT (BATCH*UK)
#define NSPLIT 8
#define PSCALE 0.044194173824159216f  // 1/sqrt(512)

__device__ float g_M[DM*DM];
__device__ float g_wkbq[DM];
__device__ float g_wvmean[DM];
__device__ float g_bvmean;
__device__ float g_G[RTOT*DM];
__device__ float g_c0[RTOT];
__device__ float g_meas[BATCH*LSEQ];
__device__ int   g_I[RTOT];
__device__ float g_H2[RTOT*DM];
__device__ float g_S[RTOT*LSEQ];
__device__ float g_AVp[NSPLIT*RTOT*DM];
__device__ float g_AV[RTOT*DM];
__device__ float g_P[4*DM*DM];   // split-K partials (max 4 x 512 x 512)

__device__ __forceinline__ unsigned sptr(const void* p) {
    return (unsigned)__cvta_generic_to_shared(p);
}
__device__ __forceinline__ void cpa16(unsigned s, const void* g) {
    asm volatile("cp.async.cg.shared.global [%0], [%1], 16;" :: "r"(s), "l"(g));
}
__device__ __forceinline__ void cpa_commit() {
    asm volatile("cp.async.commit_group;" ::: "memory");
}
__device__ __forceinline__ void cpa_wait1() {
    asm volatile("cp.async.wait_group 1;" ::: "memory");
}
__device__ __forceinline__ void cpa_wait0() {
    asm volatile("cp.async.wait_group 0;" ::: "memory");
}

// ---------------- prep: wvmean (blocks 0-31), wkbq (32-63), bvmean (64) ----------------
__global__ void prep_kernel(const float* __restrict__ WV, const float* __restrict__ bV,
                            const float* __restrict__ WK, const float* __restrict__ bQ) {
    int bid = blockIdx.x, tid = threadIdx.x;  // 512 thr
    int w = tid >> 5, lane = tid & 31;
    if (bid < 32) {
        int row = bid*16 + w;
        float s = 0.f;
        #pragma unroll
        for (int j = 0; j < 16; j++) s += WV[row*DM + lane + 32*j];
        #pragma unroll
        for (int o = 16; o > 0; o >>= 1) s += __shfl_xor_sync(~0u, s, o);
        if (lane == 0) g_wvmean[row] = s * (1.0f/DM);
    } else if (bid < 64) {
        int row = (bid-32)*16 + w;
        float s = 0.f;
        #pragma unroll
        for (int j = 0; j < 16; j++) {
            int c = lane + 32*j;
            s += WK[row*DM + c] * bQ[c];
        }
        #pragma unroll
        for (int o = 16; o > 0; o >>= 1) s += __shfl_xor_sync(~0u, s, o);
        if (lane == 0) g_wkbq[row] = s;
    } else {
        __shared__ float red[512];
        red[tid] = bV[tid]; __syncthreads();
        for (int st = 256; st > 0; st >>= 1) { if (tid < st) red[tid] += red[tid+st]; __syncthreads(); }
        if (tid == 0) g_bvmean = red[0] * (1.0f/DM);
    }
}

// ---------------- split-K gemm: P[z] = A * (B or B^T) over K chunk z*128..+128 ----------------
// GATHER: 0 none; 1 arow=(m/UK)*LSEQ+gidx[m]; 2 same w/ g_I.
template<int TRANSB, int GATHER>
__global__ void gemm512s(const float* __restrict__ A, const float* __restrict__ Bm,
                         float* __restrict__ P, long pstride,
                         int Mrows, const int* __restrict__ gidx) {
    const int BK = 32;
    __shared__ float As[2][64][36];
    __shared__ float BsT[TRANSB ? 2 : 1][TRANSB ? 64 : 1][TRANSB ? 36 : 1];
    __shared__ float BsN[TRANSB ? 1 : 2][TRANSB ? 1 : 32][TRANSB ? 1 : 68];
    int tid = threadIdx.x;  // 256
    int tx = tid & 15, ty = tid >> 4;
    int n0 = blockIdx.x * 64, m0 = blockIdx.y * 64;
    int kbase = blockIdx.z * 128;
    float acc[4][4] = {};

    auto load_tile = [&](int t, int buf) {
        int k0 = kbase + t * BK;
        #pragma unroll
        for (int j = 0; j < 2; j++) {
            int c = tid + 256*j;           // 512 chunks: 64 rows x 8 quads
            int r = c >> 3, q = c & 7;
            int mm = m0 + r;
            if (mm < Mrows) {
                int arow;
                if (GATHER == 0)      arow = mm;
                else if (GATHER == 1) arow = (mm/UK)*LSEQ + gidx[mm];
                else                  arow = (mm/UK)*LSEQ + g_I[mm];
                cpa16(sptr(&As[buf][r][q*4]), A + (long)arow*DM + k0 + q*4);
            } else {
                *(float4*)&As[buf][r][q*4] = make_float4(0.f,0.f,0.f,0.f);
            }
        }
        if (TRANSB) {
            #pragma unroll
            for (int j = 0; j < 2; j++) {
                int c = tid + 256*j;
                int r = c >> 3, q = c & 7;
                cpa16(sptr(&BsT[buf][r][q*4]), Bm + (long)(n0+r)*DM + k0 + q*4);
            }
        } else {
            #pragma unroll
            for (int j = 0; j < 2; j++) {
                int c = tid + 256*j;       // 512 chunks: 32 k x 16 quads
                int kk = c >> 4, q = c & 15;
                cpa16(sptr(&BsN[buf][kk][q*4]), Bm + (long)(k0+kk)*DM + n0 + q*4);
            }
        }
        cpa_commit();
    };

    load_tile(0, 0);
    const int NT = 128 / BK;  // 4
    for (int t = 0; t < NT; t++) {
        int buf = t & 1;
        if (t+1 < NT) { load_tile(t+1, buf^1); cpa_wait1(); } else cpa_wait0();
        __syncthreads();
        #pragma unroll
        for (int kk = 0; kk < BK; kk++) {
            float a[4], b[4];
            #pragma unroll
            for (int i = 0; i < 4; i++) a[i] = As[buf][ty + 16*i][kk];
            #pragma unroll
            for (int j = 0; j < 4; j++) b[j] = TRANSB ? BsT[buf][tx + 16*j][kk]
                                                      : BsN[buf][kk][tx + 16*j];
            #pragma unroll
            for (int i = 0; i < 4; i++)
                #pragma unroll
                for (int j = 0; j < 4; j++) acc[i][j] = fmaf(a[i], b[j], acc[i][j]);
        }
        __syncthreads();
    }
    float* Pz = P + (long)blockIdx.z * pstride;
    #pragma unroll
    for (int i = 0; i < 4; i++) {
        int mm = m0 + ty + 16*i;
        if (mm >= Mrows) continue;
        #pragma unroll
        for (int j = 0; j < 4; j++)
            Pz[(long)mm*DM + n0 + tx + 16*j] = acc[i][j];
    }
}

// ---------------- reduce 4 split-K partials (float4/thread); optional bias + scatter ----------------
template<int BIAS, int SCATTER>
__global__ void reduceP_kernel(const float* __restrict__ P, long pstride,
                               const float* __restrict__ bias, float* __restrict__ C,
                               int nelem) {
    long e = ((long)blockIdx.x*256 + threadIdx.x) * 4;
    if (e >= nelem) return;
    float4 s = *(const float4*)(P + e);
    #pragma unroll
    for (int z = 1; z < 4; z++) {
        float4 p = *(const float4*)(P + (long)z*pstride + e);
        s.x += p.x; s.y += p.y; s.z += p.z; s.w += p.w;
    }
    int col = (int)(e & (DM-1));
    if (BIAS) { s.x += bias[col]; s.y += bias[col+1]; s.z += bias[col+2]; s.w += bias[col+3]; }
    long row = e >> 9;
    if (SCATTER) row = (long)(row/UK)*LSEQ + g_I[row];
    *(float4*)(C + row*DM + col) = s;
}

// ---------------- fused: reduce M partials (blocks 0-255) + c0 (blocks 256..615) ----------------
__global__ void redM_c0_kernel(const float* __restrict__ K, const int* __restrict__ kidx) {
    int bx = blockIdx.x, tid = threadIdx.x;  // 256
    if (bx < 256) {
        long e = ((long)bx*256 + tid) * 4;
        float4 s = *(const float4*)(g_P + e);
        #pragma unroll
        for (int z = 1; z < 4; z++) {
            float4 p = *(const float4*)(g_P + (long)z*DM*DM + e);
            s.x += p.x; s.y += p.y; s.z += p.z; s.w += p.w;
        }
        *(float4*)(g_M + e) = s;
    } else {
        int r = bx - 256;
        int b = r / UK;
        const float* krow = K + ((long)b*LSEQ + kidx[r])*DM;
        float s = krow[tid]*g_wkbq[tid] + krow[tid+256]*g_wkbq[tid+256];
        int lane = tid & 31, w = tid >> 5;
        #pragma unroll
        for (int o = 16; o > 0; o >>= 1) s += __shfl_xor_sync(~0u, s, o);
        __shared__ float red[8];
        if (lane == 0) red[w] = s;
        __syncthreads();
        if (tid == 0) {
            float t = 0.f;
            #pragma unroll
            for (int i = 0; i < 8; i++) t += red[i];
            g_c0[r] = t;
        }
    }
}

// ---------------- tall46: Z[l,u]=X[b,l,:].Y[u,:] (46 virtual rows), double-buffered ----------------
template<int MODE>
__global__ void tall46(const float* __restrict__ X) {
    const int BM = 128, BK = 16, NU = 46;
    __shared__ float Xs[2][BM][20];
    __shared__ float Ys[2][NU][BK];
    __shared__ float c0s[UK];
    int b = blockIdx.y, l0 = blockIdx.x * BM, tid = threadIdx.x;  // 128
    if (MODE == 0 && tid < UK) c0s[tid] = g_c0[b*UK + tid];
    float acc[NU];
    #pragma unroll
    for (int u = 0; u < NU; u++) acc[u] = 0.f;
    const float* Xb = X + ((long)b*LSEQ + l0)*DM;

    auto load_tile = [&](int t, int buf) {
        int k0 = t * BK;
        #pragma unroll
        for (int j = 0; j < 4; j++) {
            int c = tid + 128*j;           // 512 chunks: 128 rows x 4 quads
            int r = c >> 2, q = c & 3;
            cpa16(sptr(&Xs[buf][r][q*4]), Xb + (long)r*DM + k0 + q*4);
        }
        #pragma unroll
        for (int j = 0; j < 2; j++) {
            int c = tid + 128*j;           // 184 chunks: 46 rows x 4 quads
            if (c < NU*4) {
                int u = c >> 2, q = c & 3;
                if (u < UK) {
                    const float* src = (MODE == 0) ? &g_G[(long)(b*UK+u)*DM + k0 + q*4]
                                                   : &g_H2[(long)(b*UK+u)*DM + k0 + q*4];
                    cpa16(sptr(&Ys[buf][u][q*4]), src);
                } else {
                    if (MODE == 0) *(float4*)&Ys[buf][u][q*4] = make_float4(0.f,0.f,0.f,0.f);
                    else cpa16(sptr(&Ys[buf][u][q*4]), &g_wkbq[k0 + q*4]);
                }
            }
        }
        cpa_commit();
    };

    load_tile(0, 0);
    const int NT = DM / BK;
    for (int t = 0; t < NT; t++) {
        int buf = t & 1;
        if (t+1 < NT) { load_tile(t+1, buf^1); cpa_wait1(); } else cpa_wait0();
        __syncthreads();
        #pragma unroll
        for (int c4 = 0; c4 < BK/4; c4++) {
            float4 x = *(const float4*)&Xs[buf][tid][c4*4];
            #pragma unroll
            for (int u = 0; u < NU; u++) {
                float4 y = *(const float4*)&Ys[buf][u][c4*4];
                acc[u] = fmaf(x.x, y.x, acc[u]);
                acc[u] = fmaf(x.y, y.y, acc[u]);
                acc[u] = fmaf(x.z, y.z, acc[u]);
                acc[u] = fmaf(x.w, y.w, acc[u]);
            }
        }
        __syncthreads();
    }
    int l = l0 + tid;
    if (MODE == 0) {
        float m = -INFINITY, s = 0.f;
        #pragma unroll
        for (int u = 0; u < UK; u++) {
            float v = acc[u] + c0s[u];
            m = fmaxf(m, v); s += v;
        }
        g_meas[b*LSEQ + l] = m - s*(1.0f/UK);
    } else {
        float ck = acc[UK];
        #pragma unroll
        for (int u = 0; u < UQ; u++)
            g_S[((long)b*UQ + u)*LSEQ + l] = (acc[u] + ck) * PSCALE;
    }
}

// ---------------- exact top-45 via 3-level radix select ----------------
__global__ void topk_kernel() {
    __shared__ unsigned um[LSEQ];
    __shared__ int hist[2048];
    __shared__ int eqbuf[256];
    __shared__ int s_rem, s_ngt, s_cntgt, s_cnteq;
    __shared__ unsigned s_prefmask, s_prefval;
    int b = blockIdx.x, tid = threadIdx.x;  // 512
    for (int i = tid; i < LSEQ; i += 512) {
        unsigned u = __float_as_uint(g_meas[b*LSEQ + i]);
        um[i] = (u & 0x80000000u) ? ~u : (u | 0x80000000u);
    }
    if (tid == 0) { s_rem = UQ; s_ngt = 0; s_prefmask = 0u; s_prefval = 0u; s_cntgt = 0; s_cnteq = 0; }
    __syncthreads();

    const int shifts[3] = {21, 10, 0};
    const unsigned bmask[3] = {0x7FFu, 0x7FFu, 0x3FFu};
    const int nbins[3] = {2048, 2048, 1024};
    for (int lev = 0; lev < 3; lev++) {
        for (int i = tid; i < nbins[lev]; i += 512) hist[i] = 0;
        __syncthreads();
        unsigned pm = s_prefmask, pv = s_prefval;
        for (int i = tid; i < LSEQ; i += 512) {
            unsigned k = um[i];
            if ((k & pm) == pv)
                atomicAdd(&hist[(k >> shifts[lev]) & bmask[lev]], 1);
        }
        __syncthreads();
        if (tid == 0) {
            int rem = s_rem, cum = 0, bsel = 0;
            for (int bin = nbins[lev]-1; bin >= 0; bin--) {
                cum += hist[bin];
                if (cum >= rem) { bsel = bin; break; }
            }
            s_ngt += cum - hist[bsel];
            s_rem = rem - (cum - hist[bsel]);
            s_prefmask |= bmask[lev] << shifts[lev];
            s_prefval  |= ((unsigned)bsel) << shifts[lev];
        }
        __syncthreads();
    }
    unsigned T = s_prefval;
    int n_gt = s_ngt;
    int need_eq = UQ - n_gt;
    for (int i = tid; i < LSEQ; i += 512) {
        unsigned k = um[i];
        if (k > T) {
            int p = atomicAdd(&s_cntgt, 1);
            g_I[b*UQ + p] = i;
        } else if (k == T) {
            int p = atomicAdd(&s_cnteq, 1);
            if (p < 256) eqbuf[p] = i;
        }
    }
    __syncthreads();
    if (tid == 0) {
        int ne = s_cnteq; if (ne > 256) ne = 256;
        for (int j = 0; j < need_eq; j++) {
            int bi = 0x7fffffff, bp = -1;
            for (int q = 0; q < ne; q++)
                if (eqbuf[q] < bi) { bi = eqbuf[q]; bp = q; }
            eqbuf[bp] = 0x7fffffff;
            g_I[b*UQ + n_gt + j] = bi;
        }
    }
}

// ---------------- softmax over L, register-resident ----------------
__global__ void softmax_kernel() {
    float* row = g_S + (long)blockIdx.x*LSEQ;
    int tid = threadIdx.x;  // 256
    int lane = tid & 31, w = tid >> 5;
    __shared__ float red[8];
    float v[16];
    #pragma unroll
    for (int i = 0; i < 16; i++) v[i] = row[tid + 256*i];
    float m = -INFINITY;
    #pragma unroll
    for (int i = 0; i < 16; i++) m = fmaxf(m, v[i]);
    #pragma unroll
    for (int o = 16; o > 0; o >>= 1) m = fmaxf(m, __shfl_xor_sync(~0u, m, o));
    if (lane == 0) red[w] = m;
    __syncthreads();
    m = red[0];
    #pragma unroll
    for (int i = 1; i < 8; i++) m = fmaxf(m, red[i]);
    float e[16], s = 0.f;
    #pragma unroll
    for (int i = 0; i < 16; i++) { e[i] = expf(v[i] - m); s += e[i]; }
    #pragma unroll
    for (int o = 16; o > 0; o >>= 1) s += __shfl_xor_sync(~0u, s, o);
    __syncthreads();
    if (lane == 0) red[w] = s;
    __syncthreads();
    s = 0.f;
    #pragma unroll
    for (int i = 0; i < 8; i++) s += red[i];
    float inv = 1.0f / s;
    #pragma unroll
    for (int i = 0; i < 16; i++) row[tid + 256*i] = e[i] * inv;
}

// ---------------- fused: attn@V partials (blocks 0-255) + base rows (blocks 256..4351) ----------------
__global__ void av_base_kernel(const float* __restrict__ V, float* __restrict__ out) {
    const int BKt = 32;
    __shared__ float As[2][48][36];
    __shared__ float Bs[2][32][132];
    int bid = blockIdx.x;
    int tid = threadIdx.x;  // 256
    if (bid >= 256) {
        // ---- base: out[row,:] = V[row].wvmean + bvmean ----
        int w = tid >> 5, lane = tid & 31;
        long row = (long)(bid - 256)*8 + w;
        const float4* v4 = reinterpret_cast<const float4*>(V + row*DM);
        const float4* w4 = reinterpret_cast<const float4*>(g_wvmean);
        float s = 0.f;
        #pragma unroll
        for (int i = 0; i < 4; i++) {
            float4 a = v4[lane + 32*i];
            float4 c = w4[lane + 32*i];
            s += a.x*c.x + a.y*c.y + a.z*c.z + a.w*c.w;
        }
        #pragma unroll
        for (int o = 16; o > 0; o >>= 1) s += __shfl_xor_sync(~0u, s, o);
        float r = s + g_bvmean;
        float4 ov = make_float4(r, r, r, r);
        float4* o4 = reinterpret_cast<float4*>(out + row*DM);
        #pragma unroll
        for (int i = 0; i < 4; i++) o4[lane + 32*i] = ov;
        return;
    }
    // ---- av: partial attn @ V ----
    int n0 = (bid & 3) * 128;
    int kc = (bid >> 2) & 7;
    int b  = bid >> 5;
    int tx = tid & 15, ty = tid >> 4;
    float acc[3][8] = {};
    int kbase = kc * (LSEQ/NSPLIT);

    auto load_tile = [&](int t, int buf) {
        int kg = kbase + t*BKt;
        #pragma unroll
        for (int j = 0; j < 2; j++) {
            int c = tid + 256*j;            // 384 chunks: 48 rows x 8 quads
            if (c < 384) {
                int u = c >> 3, q = c & 7;
                if (u < UQ) cpa16(sptr(&As[buf][u][q*4]), &g_S[((long)b*UQ+u)*LSEQ + kg + q*4]);
                else        *(float4*)&As[buf][u][q*4] = make_float4(0.f,0.f,0.f,0.f);
            }
        }
        #pragma unroll
        for (int j = 0; j < 4; j++) {
            int c = tid + 256*j;            // 1024 chunks: 32 k x 32 quads
            int kk = c >> 5, q = c & 31;
            cpa16(sptr(&Bs[buf][kk][q*4]), V + ((long)b*LSEQ + kg + kk)*DM + n0 + q*4);
        }
        cpa_commit();
    };

    load_tile(0, 0);
    const int NT = (LSEQ/NSPLIT)/BKt;  // 16
    for (int t = 0; t < NT; t++) {
        int buf = t & 1;
        if (t+1 < NT) { load_tile(t+1, buf^1); cpa_wait1(); } else cpa_wait0();
        __syncthreads();
        #pragma unroll
        for (int kk = 0; kk < BKt; kk++) {
            float a[3], bb[8];
            #pragma unroll
            for (int i = 0; i < 3; i++) a[i] = As[buf][ty + 16*i][kk];
            #pragma unroll
            for (int j = 0; j < 8; j++) bb[j] = Bs[buf][kk][tx + 16*j];
            #pragma unroll
            for (int i = 0; i < 3; i++)
                #pragma unroll
                for (int j = 0; j < 8; j++) acc[i][j] = fmaf(a[i], bb[j], acc[i][j]);
        }
        __syncthreads();
    }
    #pragma unroll
    for (int i = 0; i < 3; i++) {
        int u = ty + 16*i;
        if (u >= UQ) continue;
        int r = b*UQ + u;
        #pragma unroll
        for (int j = 0; j < 8; j++)
            g_AVp[((long)kc*RTOT + r)*DM + n0 + tx + 16*j] = acc[i][j];
    }
}

__global__ void avreduce_kernel() {
    long e = ((long)blockIdx.x*256 + threadIdx.x) * 4;
    if (e >= (long)RTOT*DM) return;
    float4 s = *(const float4*)(g_AVp + e);
    #pragma unroll
    for (int kc = 1; kc < NSPLIT; kc++) {
        float4 p = *(const float4*)(g_AVp + (long)kc*RTOT*DM + e);
        s.x += p.x; s.y += p.y; s.z += p.z; s.w += p.w;
    }
    *(float4*)(g_AV + e) = s;
}

extern "C" void kernel_launch(void* const* d_in, const int* in_sizes, int n_in,
                              void* d_out, int out_size) {
    (void)in_sizes; (void)n_in; (void)out_size;
    const float* Q  = (const float*)d_in[0];
    const float* K  = (const float*)d_in[1];
    const float* V  = (const float*)d_in[2];
    const float* WQ = (const float*)d_in[3];
    const float* bQ = (const float*)d_in[4];
    const float* WK = (const float*)d_in[5];
    const float* WV = (const float*)d_in[7];
    const float* bV = (const float*)d_in[8];
    const int* kidx = (const int*)d_in[9];
    float* out = (float*)d_out;

    float *pM, *pG, *pH2, *pAV, *pP;
    cudaGetSymbolAddress((void**)&pM,  g_M);
    cudaGetSymbolAddress((void**)&pG,  g_G);
    cudaGetSymbolAddress((void**)&pH2, g_H2);
    cudaGetSymbolAddress((void**)&pAV, g_AV);
    cudaGetSymbolAddress((void**)&pP,  g_P);

    prep_kernel<<<65, 512>>>(WV, bV, WK, bQ);
    // M = WQ WK^T  (split-K x4)
    gemm512s<1,0><<<dim3(8,8,4), 256>>>(WQ, WK, pP, (long)DM*DM, 512, nullptr);
    redM_c0_kernel<<<256 + RTOT, 256>>>(K, kidx);                    // reduce M + c0
    // G = K[idx] M^T
    gemm512s<1,1><<<dim3(8,6,4), 256>>>(K, pM, pP, (long)RTOT*DM, RTOT, kidx);
    reduceP_kernel<0,0><<<180, 256>>>(pP, (long)RTOT*DM, nullptr, pG, RTOT*DM);
    tall46<0><<<dim3(LSEQ/128, BATCH), 128>>>(Q);                    // meas
    topk_kernel<<<BATCH, 512>>>();
    // H2 = Q[I] M
    gemm512s<0,2><<<dim3(8,6,4), 256>>>(Q, pM, pP, (long)RTOT*DM, RTOT, nullptr);
    reduceP_kernel<0,0><<<180, 256>>>(pP, (long)RTOT*DM, nullptr, pH2, RTOT*DM);
    tall46<1><<<dim3(LSEQ/128, BATCH), 128>>>(K);                    // logits
    softmax_kernel<<<RTOT, 256>>>();
    av_base_kernel<<<256 + BATCH*LSEQ/8, 256>>>(V, out);             // attn@V partials + base
    avreduce_kernel<<<180, 256>>>();
    // s1 = AV WV + bV, scattered into out
    gemm512s<0,0><<<dim3(8,6,4), 256>>>(pAV, WV, pP, (long)RTOT*DM, RTOT, nullptr);
    reduceP_kernel<1,1><<<180, 256>>>(pP, (long)RTOT*DM, bV, out, RTOT*DM);
}